// round 1
// baseline (speedup 1.0000x reference)
#include <cuda_runtime.h>

// ASG loss: FCC (free-running) - FAC (forced alignment), mean over batch.
// Shapes fixed by the reference: B=128, T=1024, N=128, S=256.
#define BB 128
#define TT 1024
#define NN 128
#define SS 256
#define NEGF (-1e30f)
#define NTHREADS 384

__device__ float g_loss[BB];

struct SmemLayout {
    float Et[NN * NN];    // Et[i*NN + j] = exp(trans[j*NN + i])
    float xs[2][NN];      // double-buffered x[t, b, :]
    float P[NN];          // exp(alpha - M)
    float bbuf[2][SS];    // FAC beta double buffer
    float self_tr[SS];
    float next_tr[SS];
    int   tg[SS];
    float red[4];
    float red2[4];
};

__global__ __launch_bounds__(NTHREADS, 1)
void asg_main(const float* __restrict__ trans,
              const float* __restrict__ x,
              const int*   __restrict__ targets,
              const int*   __restrict__ in_len,
              const int*   __restrict__ tgt_len)
{
    extern __shared__ unsigned char smem_raw[];
    SmemLayout& sm = *reinterpret_cast<SmemLayout*>(smem_raw);

    const int b    = blockIdx.x;
    const int tid  = threadIdx.x;
    const int lane = tid & 31;
    const int wid  = tid >> 5;

    // ---- init: Et (transposed exp of transition) ----
    for (int idx = tid; idx < NN * NN; idx += NTHREADS) {
        int i = idx >> 7;
        int j = idx & (NN - 1);
        sm.Et[idx] = __expf(trans[j * NN + i]);
    }
    // targets for this batch
    for (int s = tid; s < SS; s += NTHREADS)
        sm.tg[s] = targets[b * SS + s];
    __syncthreads();
    for (int s = tid; s < SS; s += NTHREADS) {
        int c = sm.tg[s];
        int p = (s == 0) ? c : sm.tg[s - 1];
        sm.self_tr[s] = trans[c * NN + c];
        sm.next_tr[s] = trans[c * NN + p];
    }

    const int len = in_len[b];
    const float* xb = x + (size_t)b * TT * NN;

    float alpha = 0.0f;
    if (tid < NN) {
        float x0 = xb[tid];
        sm.xs[0][tid] = x0;
        sm.xs[1][tid] = xb[NN + tid];
        alpha = x0;
    }
    __syncthreads();

    const int s = tid - NN;   // FAC position for tid >= 128
    float beta = NEGF;
    if (tid >= NN) {
        beta = (s == 0) ? sm.xs[0][sm.tg[0]] : NEGF;
        sm.bbuf[0][s] = beta;
    }
    __syncthreads();

    // ---- main serial recurrence over t = 1 .. len-1 ----
    for (int t = 1; t < len; ++t) {
        const int cur = t & 1;
        const int nxt = cur ^ 1;

        float xn = 0.0f;
        float fac_new = 0.0f;

        if (tid < NN) {
            // prefetch next x row (into register; stored to smem later)
            if (t + 1 < TT) xn = __ldg(&xb[(t + 1) * NN + tid]);
            // CTA max of alpha: warp reduce then cross-warp via smem
            float m = alpha;
            m = fmaxf(m, __shfl_xor_sync(0xffffffffu, m, 16));
            m = fmaxf(m, __shfl_xor_sync(0xffffffffu, m, 8));
            m = fmaxf(m, __shfl_xor_sync(0xffffffffu, m, 4));
            m = fmaxf(m, __shfl_xor_sync(0xffffffffu, m, 2));
            m = fmaxf(m, __shfl_xor_sync(0xffffffffu, m, 1));
            if (lane == 0) sm.red[wid] = m;
        } else {
            // FAC step: reads xs[cur] and bbuf[(t-1)&1] (== nxt), both ready
            float em = sm.xs[cur][sm.tg[s]];
            float va = beta + sm.self_tr[s];
            float bl = (s == 0) ? NEGF : sm.bbuf[nxt][s - 1];
            float vb = bl + sm.next_tr[s];
            float mx = fmaxf(va, vb);
            float mn = fminf(va, vb);
            fac_new = em + mx + log1pf(__expf(mn - mx));
        }
        __syncthreads();   // red[] ready; FAC done reading bbuf[nxt]

        float M = 0.0f;
        if (tid < NN) {
            M = fmaxf(fmaxf(sm.red[0], sm.red[1]), fmaxf(sm.red[2], sm.red[3]));
            sm.P[tid] = __expf(alpha - M);
        } else {
            beta = fac_new;
            sm.bbuf[cur][s] = beta;
        }
        __syncthreads();   // P ready

        if (tid < NN) {
            // alpha'_j = x[t,j] + M + log( sum_i P[i] * Et[i][j] )
            float a0 = 0.f, a1 = 0.f, a2 = 0.f, a3 = 0.f;
            const float4* P4 = reinterpret_cast<const float4*>(sm.P);
            const float* Ej = sm.Et + tid;
#pragma unroll
            for (int i4 = 0; i4 < NN / 4; ++i4) {
                float4 pv = P4[i4];
                const float* e = Ej + i4 * 4 * NN;
                a0 = fmaf(pv.x, e[0],      a0);
                a1 = fmaf(pv.y, e[NN],     a1);
                a2 = fmaf(pv.z, e[2 * NN], a2);
                a3 = fmaf(pv.w, e[3 * NN], a3);
            }
            float acc = (a0 + a1) + (a2 + a3);
            alpha = sm.xs[cur][tid] + M + __logf(acc);
            sm.xs[nxt][tid] = xn;   // publish prefetched row t+1
        }
        __syncthreads();   // xs[nxt], bbuf[cur] visible for next iter
    }

    // ---- finalize ----
    if (tid < NN) {
        float m = alpha;
        m = fmaxf(m, __shfl_xor_sync(0xffffffffu, m, 16));
        m = fmaxf(m, __shfl_xor_sync(0xffffffffu, m, 8));
        m = fmaxf(m, __shfl_xor_sync(0xffffffffu, m, 4));
        m = fmaxf(m, __shfl_xor_sync(0xffffffffu, m, 2));
        m = fmaxf(m, __shfl_xor_sync(0xffffffffu, m, 1));
        if (lane == 0) sm.red[wid] = m;
    }
    __syncthreads();
    if (tid < NN) {
        float M = fmaxf(fmaxf(sm.red[0], sm.red[1]), fmaxf(sm.red[2], sm.red[3]));
        float p = __expf(alpha - M);
        p += __shfl_xor_sync(0xffffffffu, p, 16);
        p += __shfl_xor_sync(0xffffffffu, p, 8);
        p += __shfl_xor_sync(0xffffffffu, p, 4);
        p += __shfl_xor_sync(0xffffffffu, p, 2);
        p += __shfl_xor_sync(0xffffffffu, p, 1);
        if (lane == 0) sm.red2[wid] = p;
        if (lane == 0) sm.red[wid] = M;   // keep M around (same for all warps)
    }
    __syncthreads();
    if (tid == 0) {
        float M = sm.red[0];
        float ssum = sm.red2[0] + sm.red2[1] + sm.red2[2] + sm.red2[3];
        float fcc = M + __logf(ssum);
        int tl = tgt_len[b];
        float fac = sm.bbuf[(len - 1) & 1][tl - 1];
        g_loss[b] = fcc - fac;
    }
}

__global__ void asg_reduce(float* __restrict__ out)
{
    int t = threadIdx.x;   // 128 threads
    float v = g_loss[t];
    v += __shfl_xor_sync(0xffffffffu, v, 16);
    v += __shfl_xor_sync(0xffffffffu, v, 8);
    v += __shfl_xor_sync(0xffffffffu, v, 4);
    v += __shfl_xor_sync(0xffffffffu, v, 2);
    v += __shfl_xor_sync(0xffffffffu, v, 1);
    __shared__ float ws[4];
    if ((t & 31) == 0) ws[t >> 5] = v;
    __syncthreads();
    if (t == 0) out[0] = (ws[0] + ws[1] + ws[2] + ws[3]) * (1.0f / (float)BB);
}

extern "C" void kernel_launch(void* const* d_in, const int* in_sizes, int n_in,
                              void* d_out, int out_size)
{
    const float* trans   = (const float*)d_in[0];
    const float* x       = (const float*)d_in[1];
    const int*   targets = (const int*)d_in[2];
    const int*   in_len  = (const int*)d_in[3];
    const int*   tgt_len = (const int*)d_in[4];

    // 72.2 KB dynamic smem > 48 KB default: raise the limit (idempotent;
    // also applied on the pre-capture correctness call so capture is safe).
    cudaFuncSetAttribute(asg_main, cudaFuncAttributeMaxDynamicSharedMemorySize,
                         (int)sizeof(SmemLayout));

    asg_main<<<BB, NTHREADS, sizeof(SmemLayout)>>>(trans, x, targets, in_len, tgt_len);
    asg_reduce<<<1, 128>>>((float*)d_out);
}

// round 3
// speedup vs baseline: 1.8122x; 1.8122x over previous
#include <cuda_runtime.h>

// ASG loss: FCC (free-running) - FAC (forced alignment), mean over batch.
// B=128, T=1024, N=128, S=256.
#define BB 128
#define TT 1024
#define NN 128
#define SS 256
#define NEGF (-1e30f)
#define NTH 128

__device__ float g_loss[BB];

struct Smem {
    float P[NN];          // exp(alpha - M)
    float xs[2][NN];      // double-buffered x[t, b, :]
    float bbuf[2][SS];    // FAC beta double buffer
    float self_tr[SS];
    float next_tr[SS];
    int   tg[SS];
    float aref;           // alpha[0] reference for LSE shift
    float red[4];
    float red2[4];
};

__global__ __launch_bounds__(NTH, 1)
void asg_main(const float* __restrict__ trans,
              const float* __restrict__ x,
              const int*   __restrict__ targets,
              const int*   __restrict__ in_len,
              const int*   __restrict__ tgt_len)
{
    __shared__ Smem sm;

    const int b    = blockIdx.x;
    const int tid  = threadIdx.x;
    const int lane = tid & 31;
    const int wid  = tid >> 5;

    // ---- Et row for this thread's j=tid, kept in REGISTERS ----
    // alpha'_j = x_j + M + log( sum_i exp(alpha_i - M) * exp(trans[j,i]) )
    float Ereg[NN];
    {
        const float4* tr4 = reinterpret_cast<const float4*>(trans + tid * NN);
#pragma unroll
        for (int i4 = 0; i4 < NN / 4; ++i4) {
            float4 v = tr4[i4];
            Ereg[4 * i4 + 0] = __expf(v.x);
            Ereg[4 * i4 + 1] = __expf(v.y);
            Ereg[4 * i4 + 2] = __expf(v.z);
            Ereg[4 * i4 + 3] = __expf(v.w);
        }
    }

    // ---- targets / FAC transition scores ----
    const int s0 = tid, s1 = tid + NN;
    sm.tg[s0] = targets[b * SS + s0];
    sm.tg[s1] = targets[b * SS + s1];
    __syncthreads();
    {
        int c0 = sm.tg[s0];
        int p0 = (s0 == 0) ? c0 : sm.tg[s0 - 1];
        sm.self_tr[s0] = trans[c0 * NN + c0];
        sm.next_tr[s0] = trans[c0 * NN + p0];
        int c1 = sm.tg[s1];
        int p1 = sm.tg[s1 - 1];
        sm.self_tr[s1] = trans[c1 * NN + c1];
        sm.next_tr[s1] = trans[c1 * NN + p1];
    }

    const int len = in_len[b];
    const float* xb = x + (size_t)b * TT * NN;

    // init alpha = x0; xs buffers hold rows 0 and 1; prefetch row 2
    float alpha = xb[tid];
    sm.xs[0][tid] = alpha;
    sm.xs[1][tid] = xb[NN + tid];
    float r_pref = xb[2 * NN + tid];   // row t+1 staged for next store (t=1 -> row 2)
    if (tid == 0) sm.aref = alpha;
    __syncthreads();

    // FAC init (needs xs[0] and tg)
    float beta0 = (s0 == 0) ? sm.xs[0][sm.tg[0]] : NEGF;
    float beta1 = NEGF;
    sm.bbuf[0][s0] = beta0;
    sm.bbuf[0][s1] = beta1;
    const float st0 = sm.self_tr[s0], nt0 = sm.next_tr[s0];
    const float st1 = sm.self_tr[s1], nt1 = sm.next_tr[s1];
    const int   tg0 = sm.tg[s0],      tg1 = sm.tg[s1];
    __syncthreads();

    float M = sm.aref;

    // ---- serial recurrence t = 1 .. len-1 ; 2 barriers per step ----
    for (int t = 1; t < len; ++t) {
        const int cur = t & 1;
        const int prv = cur ^ 1;

        // prefetch row t+2 (consumed at step t+1's phase B store)
        float r_new = (t + 2 < TT) ? __ldg(&xb[(t + 2) * NN + tid]) : 0.0f;

        // ---- phase A: publish P; FAC step (reads prv buffers, writes cur) ----
        sm.P[tid] = __expf(alpha - M);
        {
            float em0 = sm.xs[cur][tg0];
            float va0 = beta0 + st0;
            float bl0 = (s0 == 0) ? NEGF : sm.bbuf[prv][s0 - 1];
            float vb0 = bl0 + nt0;
            float mx0 = fmaxf(va0, vb0), mn0 = fminf(va0, vb0);
            beta0 = em0 + mx0 + log1pf(__expf(mn0 - mx0));
            sm.bbuf[cur][s0] = beta0;

            float em1 = sm.xs[cur][tg1];
            float va1 = beta1 + st1;
            float bl1 = sm.bbuf[prv][s1 - 1];
            float vb1 = bl1 + nt1;
            float mx1 = fmaxf(va1, vb1), mn1 = fminf(va1, vb1);
            beta1 = em1 + mx1 + log1pf(__expf(mn1 - mx1));
            sm.bbuf[cur][s1] = beta1;
        }
        __syncthreads();   // P ready; bbuf[prv] fully consumed

        // ---- phase B: matvec on register-resident Et ----
        float a0 = 0.f, a1 = 0.f, a2 = 0.f, a3 = 0.f;
        const float4* P4 = reinterpret_cast<const float4*>(sm.P);
#pragma unroll
        for (int i4 = 0; i4 < NN / 4; ++i4) {
            float4 pv = P4[i4];   // broadcast LDS.128
            a0 = fmaf(pv.x, Ereg[4 * i4 + 0], a0);
            a1 = fmaf(pv.y, Ereg[4 * i4 + 1], a1);
            a2 = fmaf(pv.z, Ereg[4 * i4 + 2], a2);
            a3 = fmaf(pv.w, Ereg[4 * i4 + 3], a3);
        }
        float acc = (a0 + a1) + (a2 + a3);
        alpha = sm.xs[cur][tid] + M + __logf(acc);

        sm.xs[prv][tid] = r_pref;     // publish row t+1
        r_pref = r_new;
        if (tid == 0) sm.aref = alpha;
        __syncthreads();   // xs, aref, bbuf visible for next step

        M = sm.aref;       // note: read AFTER barrier via fresh load
    }

    // ---- finalize FCC: exact logsumexp over alpha ----
    float m = alpha;
    m = fmaxf(m, __shfl_xor_sync(0xffffffffu, m, 16));
    m = fmaxf(m, __shfl_xor_sync(0xffffffffu, m, 8));
    m = fmaxf(m, __shfl_xor_sync(0xffffffffu, m, 4));
    m = fmaxf(m, __shfl_xor_sync(0xffffffffu, m, 2));
    m = fmaxf(m, __shfl_xor_sync(0xffffffffu, m, 1));
    if (lane == 0) sm.red[wid] = m;
    __syncthreads();
    float Mf = fmaxf(fmaxf(sm.red[0], sm.red[1]), fmaxf(sm.red[2], sm.red[3]));
    float p = __expf(alpha - Mf);
    p += __shfl_xor_sync(0xffffffffu, p, 16);
    p += __shfl_xor_sync(0xffffffffu, p, 8);
    p += __shfl_xor_sync(0xffffffffu, p, 4);
    p += __shfl_xor_sync(0xffffffffu, p, 2);
    p += __shfl_xor_sync(0xffffffffu, p, 1);
    if (lane == 0) sm.red2[wid] = p;
    __syncthreads();
    if (tid == 0) {
        float ssum = sm.red2[0] + sm.red2[1] + sm.red2[2] + sm.red2[3];
        float fcc = Mf + __logf(ssum);
        int tl = tgt_len[b];
        float fac = sm.bbuf[(len - 1) & 1][tl - 1];
        g_loss[b] = fcc - fac;
    }
}

__global__ void asg_reduce(float* __restrict__ out)
{
    int t = threadIdx.x;   // 128 threads
    float v = g_loss[t];
    v += __shfl_xor_sync(0xffffffffu, v, 16);
    v += __shfl_xor_sync(0xffffffffu, v, 8);
    v += __shfl_xor_sync(0xffffffffu, v, 4);
    v += __shfl_xor_sync(0xffffffffu, v, 2);
    v += __shfl_xor_sync(0xffffffffu, v, 1);
    __shared__ float ws[4];
    if ((t & 31) == 0) ws[t >> 5] = v;
    __syncthreads();
    if (t == 0) out[0] = (ws[0] + ws[1] + ws[2] + ws[3]) * (1.0f / (float)BB);
}

extern "C" void kernel_launch(void* const* d_in, const int* in_sizes, int n_in,
                              void* d_out, int out_size)
{
    const float* trans   = (const float*)d_in[0];
    const float* x       = (const float*)d_in[1];
    const int*   targets = (const int*)d_in[2];
    const int*   in_len  = (const int*)d_in[3];
    const int*   tgt_len = (const int*)d_in[4];

    asg_main<<<BB, NTH>>>(trans, x, targets, in_len, tgt_len);
    asg_reduce<<<1, 128>>>((float*)d_out);
}

// round 4
// speedup vs baseline: 2.1720x; 1.1986x over previous
#include <cuda_runtime.h>

// ASG loss: FCC (free-running) - FAC (forced alignment), mean over batch.
// B=128, T=1024, N=128, S=256.
#define BB 128
#define TT 1024
#define NN 128
#define SS 256
#define NEGF (-1e30f)
#define NTH 256   // warps 0-3: FCC (j = tid), warps 4-7: FAC (2 positions each)

__device__ float g_loss[BB];

struct __align__(16) Smem {
    float P[NN];          // exp(alpha - M), 16B-aligned for ulonglong2 loads
    float xs[2][NN];      // double-buffered x[t, b, :]
    float bbuf[2][SS];    // FAC beta double buffer
    float self_tr[SS];
    float next_tr[SS];
    int   tg[SS];
    float aref;           // alpha[0] reference for LSE shift
    float red[4];
    float red2[4];
};

__device__ __forceinline__ unsigned long long pack2(float lo, float hi) {
    unsigned long long r;
    asm("mov.b64 %0, {%1, %2};" : "=l"(r) : "f"(lo), "f"(hi));
    return r;
}
__device__ __forceinline__ void unpack2(float& lo, float& hi, unsigned long long v) {
    asm("mov.b64 {%0, %1}, %2;" : "=f"(lo), "=f"(hi) : "l"(v));
}
#define FMA2(acc, a, b) \
    asm("fma.rn.f32x2 %0, %1, %2, %0;" : "+l"(acc) : "l"(a), "l"(b))

__global__ __launch_bounds__(NTH, 1)
void asg_main(const float* __restrict__ trans,
              const float* __restrict__ x,
              const int*   __restrict__ targets,
              const int*   __restrict__ in_len,
              const int*   __restrict__ tgt_len)
{
    __shared__ Smem sm;

    const int b    = blockIdx.x;
    const int tid  = threadIdx.x;
    const int lane = tid & 31;
    const int wid  = tid >> 5;

    const int len = in_len[b];
    const float* xb = x + (size_t)b * TT * NN;

    // targets: one per thread
    sm.tg[tid] = targets[b * SS + tid];

    // ---- FCC threads: Et row (exp of trans[j,:]) packed f32x2 in REGISTERS ----
    unsigned long long E2[NN / 2];
    float alpha = 0.0f, r_pref = 0.0f;
    if (tid < NN) {
        const float4* tr4 = reinterpret_cast<const float4*>(trans + tid * NN);
#pragma unroll
        for (int i4 = 0; i4 < NN / 4; ++i4) {
            float4 v = tr4[i4];
            E2[2 * i4 + 0] = pack2(__expf(v.x), __expf(v.y));
            E2[2 * i4 + 1] = pack2(__expf(v.z), __expf(v.w));
        }
        alpha = xb[tid];
        sm.xs[0][tid] = alpha;
        sm.xs[1][tid] = xb[NN + tid];
        r_pref = xb[2 * NN + tid];           // row t+1 staged (published at t=1)
        if (tid == 0) sm.aref = alpha;
    }
    __syncthreads();   // tg + xs[0] visible

    // ---- FAC thread state (warps 4-7): positions s0 = ft, s1 = ft + 128 ----
    const int ft = tid - NN;
    float beta0 = NEGF, beta1 = NEGF;
    float st0 = 0.f, nt0 = 0.f, st1 = 0.f, nt1 = 0.f;
    int   tg0 = 0, tg1 = 0;
    if (tid >= NN) {
        const int s0 = ft, s1 = ft + NN;
        tg0 = sm.tg[s0];
        tg1 = sm.tg[s1];
        int p0 = (s0 == 0) ? tg0 : sm.tg[s0 - 1];
        int p1 = sm.tg[s1 - 1];
        st0 = trans[tg0 * NN + tg0];
        nt0 = trans[tg0 * NN + p0];
        st1 = trans[tg1 * NN + tg1];
        nt1 = trans[tg1 * NN + p1];
        beta0 = (s0 == 0) ? sm.xs[0][tg0] : NEGF;
        sm.bbuf[0][s0] = beta0;
        sm.bbuf[0][s1] = beta1;
    }
    __syncthreads();

    // ---- serial recurrence t = 1 .. len-1 ----
    for (int t = 1; t < len; ++t) {
        const int cur = t & 1;
        const int prv = cur ^ 1;

        if (tid < NN) {
            // phase A: everything needed is already published (prev full barrier)
            float M    = sm.aref;
            float xcur = sm.xs[cur][tid];                    // hoisted: written >=1 step ago
            float r_new = (t + 2 < TT) ? __ldg(&xb[(t + 2) * NN + tid]) : 0.0f;
            sm.P[tid] = __expf(alpha - M);
            asm volatile("bar.sync 1, 128;" ::: "memory");   // FCC-only: P ready

            // phase B: packed-f32x2 matvec on register-resident Et
            unsigned long long a0 = 0ull, a1 = 0ull, a2 = 0ull, a3 = 0ull;
            const ulonglong2* P2 = reinterpret_cast<const ulonglong2*>(sm.P);
#pragma unroll
            for (int k = 0; k < NN / 8; ++k) {               // 16 iters
                ulonglong2 p01 = P2[2 * k];
                ulonglong2 p23 = P2[2 * k + 1];
                FMA2(a0, p01.x, E2[4 * k + 0]);
                FMA2(a1, p01.y, E2[4 * k + 1]);
                FMA2(a2, p23.x, E2[4 * k + 2]);
                FMA2(a3, p23.y, E2[4 * k + 3]);
            }
            float l0, h0, l1, h1, l2, h2, l3, h3;
            unpack2(l0, h0, a0); unpack2(l1, h1, a1);
            unpack2(l2, h2, a2); unpack2(l3, h3, a3);
            float acc = ((l0 + h0) + (l1 + h1)) + ((l2 + h2) + (l3 + h3));
            alpha = xcur + M + __logf(acc);

            sm.xs[prv][tid] = r_pref;                        // publish row t+1
            r_pref = r_new;
            if (tid == 0) sm.aref = alpha;
        } else {
            // FAC full step — overlaps FCC's matvec on the shared SMSPs
            const int s0 = ft, s1 = ft + NN;
            float em0 = sm.xs[cur][tg0];
            float em1 = sm.xs[cur][tg1];
            float bl0 = (s0 == 0) ? NEGF : sm.bbuf[prv][s0 - 1];
            float bl1 = sm.bbuf[prv][s1 - 1];

            float va0 = beta0 + st0, vb0 = bl0 + nt0;
            float mx0 = fmaxf(va0, vb0), mn0 = fminf(va0, vb0);
            beta0 = em0 + mx0 + log1pf(__expf(mn0 - mx0));
            sm.bbuf[cur][s0] = beta0;

            float va1 = beta1 + st1, vb1 = bl1 + nt1;
            float mx1 = fmaxf(va1, vb1), mn1 = fminf(va1, vb1);
            beta1 = em1 + mx1 + log1pf(__expf(mn1 - mx1));
            sm.bbuf[cur][s1] = beta1;
        }
        __syncthreads();   // xs, aref, bbuf visible for next step
    }

    // ---- finalize FCC: exact logsumexp over alpha (warps 0-3) ----
    if (tid < NN) {
        float m = alpha;
        m = fmaxf(m, __shfl_xor_sync(0xffffffffu, m, 16));
        m = fmaxf(m, __shfl_xor_sync(0xffffffffu, m, 8));
        m = fmaxf(m, __shfl_xor_sync(0xffffffffu, m, 4));
        m = fmaxf(m, __shfl_xor_sync(0xffffffffu, m, 2));
        m = fmaxf(m, __shfl_xor_sync(0xffffffffu, m, 1));
        if (lane == 0) sm.red[wid] = m;
    }
    __syncthreads();
    if (tid < NN) {
        float Mf = fmaxf(fmaxf(sm.red[0], sm.red[1]), fmaxf(sm.red[2], sm.red[3]));
        float p = __expf(alpha - Mf);
        p += __shfl_xor_sync(0xffffffffu, p, 16);
        p += __shfl_xor_sync(0xffffffffu, p, 8);
        p += __shfl_xor_sync(0xffffffffu, p, 4);
        p += __shfl_xor_sync(0xffffffffu, p, 2);
        p += __shfl_xor_sync(0xffffffffu, p, 1);
        if (lane == 0) { sm.red2[wid] = p; sm.red[wid] = Mf; }
    }
    __syncthreads();
    if (tid == 0) {
        float ssum = sm.red2[0] + sm.red2[1] + sm.red2[2] + sm.red2[3];
        float fcc = sm.red[0] + __logf(ssum);
        int tl = tgt_len[b];
        float fac = sm.bbuf[(len - 1) & 1][tl - 1];
        g_loss[b] = fcc - fac;
    }
}

__global__ void asg_reduce(float* __restrict__ out)
{
    int t = threadIdx.x;   // 128 threads
    float v = g_loss[t];
    v += __shfl_xor_sync(0xffffffffu, v, 16);
    v += __shfl_xor_sync(0xffffffffu, v, 8);
    v += __shfl_xor_sync(0xffffffffu, v, 4);
    v += __shfl_xor_sync(0xffffffffu, v, 2);
    v += __shfl_xor_sync(0xffffffffu, v, 1);
    __shared__ float ws[4];
    if ((t & 31) == 0) ws[t >> 5] = v;
    __syncthreads();
    if (t == 0) out[0] = (ws[0] + ws[1] + ws[2] + ws[3]) * (1.0f / (float)BB);
}

extern "C" void kernel_launch(void* const* d_in, const int* in_sizes, int n_in,
                              void* d_out, int out_size)
{
    const float* trans   = (const float*)d_in[0];
    const float* x       = (const float*)d_in[1];
    const int*   targets = (const int*)d_in[2];
    const int*   in_len  = (const int*)d_in[3];
    const int*   tgt_len = (const int*)d_in[4];

    asg_main<<<BB, NTH>>>(trans, x, targets, in_len, tgt_len);
    asg_reduce<<<1, 128>>>((float*)d_out);
}

// round 5
// speedup vs baseline: 2.8890x; 1.3301x over previous
#include <cuda_runtime.h>

// ASG loss: FCC (free-running) - FAC (forced alignment), mean over batch.
// B=128, T=1024, N=128, S=256.
#define BB 128
#define TT 1024
#define NN 128
#define SS 256
#define NEGF (-1e30f)
#define NTH 256   // warps 0-3: FCC (j = tid), warps 4-7: FAC (2 positions each)

__device__ float g_loss[BB];

struct __align__(16) Smem {
    float Pb[2][NN];      // ping-pong P = exp(alpha - sigma)
    float bbuf[2][SS];    // FAC beta double buffer
    int   tg[SS];
    float arefbuf[2];     // ping-pong LSE reference (alpha_0, one step stale)
    float red[4];
    float red2[4];
};

__device__ __forceinline__ unsigned long long pack2(float lo, float hi) {
    unsigned long long r;
    asm("mov.b64 %0, {%1, %2};" : "=l"(r) : "f"(lo), "f"(hi));
    return r;
}
__device__ __forceinline__ void unpack2(float& lo, float& hi, unsigned long long v) {
    asm("mov.b64 {%0, %1}, %2;" : "=f"(lo), "=f"(hi) : "l"(v));
}
#define FMA2(acc, a, b) \
    asm("fma.rn.f32x2 %0, %1, %2, %0;" : "+l"(acc) : "l"(a), "l"(b))

__global__ void asg_noop() {}

__global__ __launch_bounds__(NTH, 1)
void asg_main(const float* __restrict__ trans,
              const float* __restrict__ x,
              const int*   __restrict__ targets,
              const int*   __restrict__ in_len,
              const int*   __restrict__ tgt_len)
{
    __shared__ Smem sm;

    const int b    = blockIdx.x;
    const int tid  = threadIdx.x;
    const int lane = tid & 31;
    const int wid  = tid >> 5;

    const int len = in_len[b];
    const float* xb = x + (size_t)b * TT * NN;

    sm.tg[tid] = targets[b * SS + tid];

    // ---- FCC threads: Et row (exp of trans[j,:]) packed f32x2 in registers ----
    unsigned long long E2[NN / 2];
    float alpha = 0.0f, xc1 = 0.0f, xc2 = 0.0f;
    if (tid < NN) {
        const float4* tr4 = reinterpret_cast<const float4*>(trans + tid * NN);
#pragma unroll
        for (int i4 = 0; i4 < NN / 4; ++i4) {
            float4 v = tr4[i4];
            E2[2 * i4 + 0] = pack2(__expf(v.x), __expf(v.y));
            E2[2 * i4 + 1] = pack2(__expf(v.z), __expf(v.w));
        }
        alpha = xb[tid];                 // x row 0
        xc1   = xb[NN + tid];            // x row 1
        xc2   = xb[2 * NN + tid];        // x row 2
        if (tid == 0) sm.arefbuf[1] = alpha;   // sigma_1 = alpha_0(0)
    }
    __syncthreads();   // tg + arefbuf[1] visible

    // ---- FAC thread state (warps 4-7): positions s0 = ft, s1 = ft + 128 ----
    const int ft = tid - NN;
    float beta0 = NEGF, beta1 = NEGF;
    float st0 = 0.f, nt0 = 0.f, st1 = 0.f, nt1 = 0.f;
    int   tg0 = 0, tg1 = 0;
    float em0c = 0.f, em0n = 0.f, em1c = 0.f, em1n = 0.f;
    float S_prev = 0.0f;
    if (tid < NN) {
        S_prev = sm.arefbuf[1];                   // sigma_0 = alpha_0(0)
        sm.Pb[0][tid] = __expf(alpha - S_prev);   // P(0)
    } else {
        const int s0 = ft, s1 = ft + NN;
        tg0 = sm.tg[s0];
        tg1 = sm.tg[s1];
        int p0 = (s0 == 0) ? tg0 : sm.tg[s0 - 1];
        int p1 = sm.tg[s1 - 1];
        st0 = trans[tg0 * NN + tg0];
        nt0 = trans[tg0 * NN + p0];
        st1 = trans[tg1 * NN + tg1];
        nt1 = trans[tg1 * NN + p1];
        beta0 = (s0 == 0) ? __ldg(&xb[tg0]) : NEGF;
        sm.bbuf[0][s0] = beta0;
        sm.bbuf[0][s1] = beta1;
        // emission pipeline: rows 1 and 2
        em0c = __ldg(&xb[NN + tg0]);
        em1c = __ldg(&xb[NN + tg1]);
        em0n = __ldg(&xb[2 * NN + tg0]);
        em1n = __ldg(&xb[2 * NN + tg1]);
    }
    __syncthreads();   // Pb[0], bbuf[0] visible

    if (tid < NN) {
        // ================= FCC loop: ONE barrier per step =================
        for (int t = 1; t < len; ++t) {
            const int rd = (t - 1) & 1;
            const int wr = t & 1;

            float S_cur = sm.arefbuf[wr];   // sigma_t (published at step t-1)
            float xnew = (t + 2 < TT) ? __ldg(&xb[(t + 2) * NN + tid]) : 0.0f;

            unsigned long long a0 = 0ull, a1 = 0ull, a2 = 0ull, a3 = 0ull;
            const ulonglong2* P2 = reinterpret_cast<const ulonglong2*>(sm.Pb[rd]);
#pragma unroll
            for (int k = 0; k < NN / 8; ++k) {       // 16 iters
                ulonglong2 p01 = P2[2 * k];
                ulonglong2 p23 = P2[2 * k + 1];
                FMA2(a0, p01.x, E2[4 * k + 0]);
                FMA2(a1, p01.y, E2[4 * k + 1]);
                FMA2(a2, p23.x, E2[4 * k + 2]);
                FMA2(a3, p23.y, E2[4 * k + 3]);
            }
            float l0, h0, l1, h1, l2, h2, l3, h3;
            unpack2(l0, h0, a0); unpack2(l1, h1, a1);
            unpack2(l2, h2, a2); unpack2(l3, h3, a3);
            float acc = ((l0 + h0) + (l1 + h1)) + ((l2 + h2) + (l3 + h3));

            alpha = xc1 + S_prev + __logf(acc);      // P(t-1) was shifted by S_prev
            sm.Pb[wr][tid] = __expf(alpha - S_cur);  // P(t) shifted by sigma_t
            if (tid == 0) sm.arefbuf[(t + 1) & 1] = alpha;  // sigma_{t+1}

            S_prev = S_cur;
            xc1 = xc2;
            xc2 = xnew;
            asm volatile("bar.sync 1, 128;" ::: "memory");
        }
    } else {
        // ================= FAC loop: decoupled, own barrier =================
        const int s0 = ft, s1 = ft + NN;
        for (int t = 1; t < len; ++t) {
            const int rd = (t - 1) & 1;
            const int wr = t & 1;

            float em0n2 = 0.f, em1n2 = 0.f;
            if (t + 2 < TT) {
                em0n2 = __ldg(&xb[(t + 2) * NN + tg0]);
                em1n2 = __ldg(&xb[(t + 2) * NN + tg1]);
            }
            float bl0 = (s0 == 0) ? NEGF : sm.bbuf[rd][s0 - 1];
            float bl1 = sm.bbuf[rd][s1 - 1];

            float va0 = beta0 + st0, vb0 = bl0 + nt0;
            float mx0 = fmaxf(va0, vb0), mn0 = fminf(va0, vb0);
            beta0 = em0c + mx0 + __logf(1.0f + __expf(mn0 - mx0));
            sm.bbuf[wr][s0] = beta0;

            float va1 = beta1 + st1, vb1 = bl1 + nt1;
            float mx1 = fmaxf(va1, vb1), mn1 = fminf(va1, vb1);
            beta1 = em1c + mx1 + __logf(1.0f + __expf(mn1 - mx1));
            sm.bbuf[wr][s1] = beta1;

            em0c = em0n; em0n = em0n2;
            em1c = em1n; em1n = em1n2;
            asm volatile("bar.sync 2, 128;" ::: "memory");
        }
    }

    __syncthreads();   // join FCC + FAC

    // ---- finalize FCC: exact logsumexp over alpha (warps 0-3) ----
    if (tid < NN) {
        float m = alpha;
        m = fmaxf(m, __shfl_xor_sync(0xffffffffu, m, 16));
        m = fmaxf(m, __shfl_xor_sync(0xffffffffu, m, 8));
        m = fmaxf(m, __shfl_xor_sync(0xffffffffu, m, 4));
        m = fmaxf(m, __shfl_xor_sync(0xffffffffu, m, 2));
        m = fmaxf(m, __shfl_xor_sync(0xffffffffu, m, 1));
        if (lane == 0) sm.red[wid] = m;
    }
    __syncthreads();
    if (tid < NN) {
        float Mf = fmaxf(fmaxf(sm.red[0], sm.red[1]), fmaxf(sm.red[2], sm.red[3]));
        float p = __expf(alpha - Mf);
        p += __shfl_xor_sync(0xffffffffu, p, 16);
        p += __shfl_xor_sync(0xffffffffu, p, 8);
        p += __shfl_xor_sync(0xffffffffu, p, 4);
        p += __shfl_xor_sync(0xffffffffu, p, 2);
        p += __shfl_xor_sync(0xffffffffu, p, 1);
        if (lane == 0) { sm.red2[wid] = p; sm.red[wid] = Mf; }
    }
    __syncthreads();
    if (tid == 0) {
        float ssum = sm.red2[0] + sm.red2[1] + sm.red2[2] + sm.red2[3];
        float fcc = sm.red[0] + __logf(ssum);
        int tl = tgt_len[b];
        float fac = sm.bbuf[(len - 1) & 1][tl - 1];
        g_loss[b] = fcc - fac;
    }
}

__global__ void asg_reduce(float* __restrict__ out)
{
    int t = threadIdx.x;   // 128 threads
    float v = g_loss[t];
    v += __shfl_xor_sync(0xffffffffu, v, 16);
    v += __shfl_xor_sync(0xffffffffu, v, 8);
    v += __shfl_xor_sync(0xffffffffu, v, 4);
    v += __shfl_xor_sync(0xffffffffu, v, 2);
    v += __shfl_xor_sync(0xffffffffu, v, 1);
    __shared__ float ws[4];
    if ((t & 31) == 0) ws[t >> 5] = v;
    __syncthreads();
    if (t == 0) out[0] = (ws[0] + ws[1] + ws[2] + ws[3]) * (1.0f / (float)BB);
}

extern "C" void kernel_launch(void* const* d_in, const int* in_sizes, int n_in,
                              void* d_out, int out_size)
{
    const float* trans   = (const float*)d_in[0];
    const float* x       = (const float*)d_in[1];
    const int*   targets = (const int*)d_in[2];
    const int*   in_len  = (const int*)d_in[3];
    const int*   tgt_len = (const int*)d_in[4];

    // 5 no-op launches so ncu's "-s 5 -c 1" capture lands on asg_main
    // (launch index 5 overall). Strip once tuning converges.
    for (int i = 0; i < 5; ++i) asg_noop<<<1, 1>>>();

    asg_main<<<BB, NTH>>>(trans, x, targets, in_len, tgt_len);
    asg_reduce<<<1, 128>>>((float*)d_out);
}

// round 6
// speedup vs baseline: 3.0915x; 1.0701x over previous
#include <cuda_runtime.h>

// ASG loss: FCC (free-running) - FAC (forced alignment), mean over batch.
// B=128, T=1024, N=128, S=256.
#define BB 128
#define TT 1024
#define NN 128
#define SS 256
#define NEGF (-1e30f)
#define NTH 256   // warps 0-3: FAC (2 positions each), warps 4-7: FCC (j = tid-128)

__device__ float g_loss[BB];

struct __align__(16) Smem {
    float Pb[2][NN];      // ping-pong P = exp(alpha - sig)
    float bbuf[2][SS];    // FAC beta double buffer
    int   tg[SS];
    float ubuf[2];        // ping-pong u(t) = sig(t+1) - sig(t)
    float red[4];
    float red2[4];
};

__device__ __forceinline__ unsigned long long pack2(float lo, float hi) {
    unsigned long long r;
    asm("mov.b64 %0, {%1, %2};" : "=l"(r) : "f"(lo), "f"(hi));
    return r;
}
__device__ __forceinline__ void unpack2(float& lo, float& hi, unsigned long long v) {
    asm("mov.b64 {%0, %1}, %2;" : "=f"(lo), "=f"(hi) : "l"(v));
}
#define FMA2(acc, a, b) \
    asm("fma.rn.f32x2 %0, %1, %2, %0;" : "+l"(acc) : "l"(a), "l"(b))

__global__ void asg_noop() {}

__global__ __launch_bounds__(NTH, 1)
void asg_main(const float* __restrict__ trans,
              const float* __restrict__ x,
              const int*   __restrict__ targets,
              const int*   __restrict__ in_len,
              const int*   __restrict__ tgt_len)
{
    __shared__ Smem sm;

    const int b    = blockIdx.x;
    const int tid  = threadIdx.x;
    const int lane = tid & 31;
    const int wid  = tid >> 5;

    const int len = in_len[b];
    const float* xb = x + (size_t)b * TT * NN;

    sm.tg[tid] = targets[b * SS + tid];

    // =========== FCC init (warps 4-7, j = tid - 128) ===========
    unsigned long long E2[NN / 2];
    const int j = tid - NN;
    float xc1 = 0.f, xc2 = 0.f;       // x rows t, t+1 (register pipeline)
    float sig_run = 0.f;              // sig(t-1) entering iter t
    float alphaF = 0.f;               // final alpha (reconstructed)
    if (tid >= NN) {
        const float4* tr4 = reinterpret_cast<const float4*>(trans + j * NN);
#pragma unroll
        for (int i4 = 0; i4 < NN / 4; ++i4) {
            float4 v = tr4[i4];
            E2[2 * i4 + 0] = pack2(__expf(v.x), __expf(v.y));
            E2[2 * i4 + 1] = pack2(__expf(v.z), __expf(v.w));
        }
        float a0 = xb[j];              // alpha_j(0) = x_j(0)
        sig_run  = __ldg(&xb[0]);      // sig(0) = alpha_0(0)
        alphaF   = a0;
        xc1 = xb[NN + j];
        xc2 = xb[2 * NN + j];
        sm.Pb[0][j] = __expf(a0 - sig_run);   // P(0)
        if (j == 0) { sm.ubuf[0] = 0.0f; }    // u(0) = sig(1)-sig(0) = 0
    }
    __syncthreads();   // tg, Pb[0], ubuf[0] visible

    // =========== FAC init (warps 0-3): positions s0 = tid, s1 = tid + 128 ===========
    float beta0 = NEGF, beta1 = NEGF;
    float st0 = 0.f, nt0 = 0.f, st1 = 0.f, nt1 = 0.f;
    int   tg0 = 0, tg1 = 0;
    float em0c = 0.f, em0n = 0.f, em1c = 0.f, em1n = 0.f;
    if (tid < NN) {
        const int s0 = tid, s1 = tid + NN;
        tg0 = sm.tg[s0];
        tg1 = sm.tg[s1];
        int p0 = (s0 == 0) ? tg0 : sm.tg[s0 - 1];
        int p1 = sm.tg[s1 - 1];
        st0 = trans[tg0 * NN + tg0];
        nt0 = trans[tg0 * NN + p0];
        st1 = trans[tg1 * NN + tg1];
        nt1 = trans[tg1 * NN + p1];
        beta0 = (s0 == 0) ? __ldg(&xb[tg0]) : NEGF;
        sm.bbuf[0][s0] = beta0;
        sm.bbuf[0][s1] = beta1;
        em0c = __ldg(&xb[NN + tg0]);
        em1c = __ldg(&xb[NN + tg1]);
        em0n = __ldg(&xb[2 * NN + tg0]);
        em1n = __ldg(&xb[2 * NN + tg1]);
    }
    __syncthreads();   // bbuf[0] visible

    if (tid >= NN) {
        // ============ FCC loop: no exp/log on the critical path ============
        float xA = 0.f, sigA = 0.f, accA = 1.0f;   // for final alpha reconstruction
        for (int t = 1; t < len; ++t) {
            const int rd = (t - 1) & 1;
            const int wr = t & 1;

            float u_prev = sm.ubuf[rd];            // u(t-1), published at t-1
            float K = __expf(xc1 - u_prev);        // off critical path
            float xnew = (t + 2 < TT) ? __ldg(&xb[(t + 2) * NN + j]) : 0.0f;

            unsigned long long a0 = 0ull, a1 = 0ull, a2 = 0ull, a3 = 0ull;
            const ulonglong2* P2 = reinterpret_cast<const ulonglong2*>(sm.Pb[rd]);
#pragma unroll
            for (int k = 0; k < NN / 8; ++k) {     // 16 iters
                ulonglong2 p01 = P2[2 * k];
                ulonglong2 p23 = P2[2 * k + 1];
                FMA2(a0, p01.x, E2[4 * k + 0]);
                FMA2(a1, p01.y, E2[4 * k + 1]);
                FMA2(a2, p23.x, E2[4 * k + 2]);
                FMA2(a3, p23.y, E2[4 * k + 3]);
            }
            float l0, h0, l1, h1, l2, h2, l3, h3;
            unpack2(l0, h0, a0); unpack2(l1, h1, a1);
            unpack2(l2, h2, a2); unpack2(l3, h3, a3);
            float acc = ((l0 + h0) + (l1 + h1)) + ((l2 + h2) + (l3 + h3));

            sm.Pb[wr][j] = K * acc;                // critical-path tail: 1 FMUL + STS
            if (j == 0)                            // u(t) = log(acc_0)+x_0(t)-u(t-1)
                sm.ubuf[wr] = __logf(acc) + xc1 - u_prev;

            xA = xc1; sigA = sig_run; accA = acc;  // state for alpha(t) reconstruction
            sig_run += u_prev;                     // sig(t) = sig(t-1) + u(t-1)
            xc1 = xc2; xc2 = xnew;
            asm volatile("bar.sync 1, 128;" ::: "memory");
        }
        if (len > 1) alphaF = xA + sigA + __logf(accA);
    } else {
        // ============ FAC loop: decoupled, own barrier ============
        const int s0 = tid, s1 = tid + NN;
        for (int t = 1; t < len; ++t) {
            const int rd = (t - 1) & 1;
            const int wr = t & 1;

            float em0n2 = 0.f, em1n2 = 0.f;
            if (t + 2 < TT) {
                em0n2 = __ldg(&xb[(t + 2) * NN + tg0]);
                em1n2 = __ldg(&xb[(t + 2) * NN + tg1]);
            }
            float bl0 = (s0 == 0) ? NEGF : sm.bbuf[rd][s0 - 1];
            float bl1 = sm.bbuf[rd][s1 - 1];

            float va0 = beta0 + st0, vb0 = bl0 + nt0;
            float mx0 = fmaxf(va0, vb0), mn0 = fminf(va0, vb0);
            beta0 = em0c + mx0 + __logf(1.0f + __expf(mn0 - mx0));
            sm.bbuf[wr][s0] = beta0;

            float va1 = beta1 + st1, vb1 = bl1 + nt1;
            float mx1 = fmaxf(va1, vb1), mn1 = fminf(va1, vb1);
            beta1 = em1c + mx1 + __logf(1.0f + __expf(mn1 - mx1));
            sm.bbuf[wr][s1] = beta1;

            em0c = em0n; em0n = em0n2;
            em1c = em1n; em1n = em1n2;
            asm volatile("bar.sync 2, 128;" ::: "memory");
        }
    }

    __syncthreads();   // join FCC + FAC

    // ---- finalize FCC: exact logsumexp over alphaF (warps 4-7) ----
    if (tid >= NN) {
        float m = alphaF;
        m = fmaxf(m, __shfl_xor_sync(0xffffffffu, m, 16));
        m = fmaxf(m, __shfl_xor_sync(0xffffffffu, m, 8));
        m = fmaxf(m, __shfl_xor_sync(0xffffffffu, m, 4));
        m = fmaxf(m, __shfl_xor_sync(0xffffffffu, m, 2));
        m = fmaxf(m, __shfl_xor_sync(0xffffffffu, m, 1));
        if (lane == 0) sm.red[wid - 4] = m;
    }
    __syncthreads();
    if (tid >= NN) {
        float Mf = fmaxf(fmaxf(sm.red[0], sm.red[1]), fmaxf(sm.red[2], sm.red[3]));
        float p = __expf(alphaF - Mf);
        p += __shfl_xor_sync(0xffffffffu, p, 16);
        p += __shfl_xor_sync(0xffffffffu, p, 8);
        p += __shfl_xor_sync(0xffffffffu, p, 4);
        p += __shfl_xor_sync(0xffffffffu, p, 2);
        p += __shfl_xor_sync(0xffffffffu, p, 1);
        if (lane == 0) { sm.red2[wid - 4] = p; sm.red[wid - 4] = Mf; }
    }
    __syncthreads();
    if (tid == 0) {
        float ssum = sm.red2[0] + sm.red2[1] + sm.red2[2] + sm.red2[3];
        float fcc = sm.red[0] + __logf(ssum);
        int tl = tgt_len[b];
        float fac = sm.bbuf[(len - 1) & 1][tl - 1];
        g_loss[b] = fcc - fac;
    }
}

__global__ void asg_reduce(float* __restrict__ out)
{
    int t = threadIdx.x;   // 128 threads
    float v = g_loss[t];
    v += __shfl_xor_sync(0xffffffffu, v, 16);
    v += __shfl_xor_sync(0xffffffffu, v, 8);
    v += __shfl_xor_sync(0xffffffffu, v, 4);
    v += __shfl_xor_sync(0xffffffffu, v, 2);
    v += __shfl_xor_sync(0xffffffffu, v, 1);
    __shared__ float ws[4];
    if ((t & 31) == 0) ws[t >> 5] = v;
    __syncthreads();
    if (t == 0) out[0] = (ws[0] + ws[1] + ws[2] + ws[3]) * (1.0f / (float)BB);
}

extern "C" void kernel_launch(void* const* d_in, const int* in_sizes, int n_in,
                              void* d_out, int out_size)
{
    const float* trans   = (const float*)d_in[0];
    const float* x       = (const float*)d_in[1];
    const int*   targets = (const int*)d_in[2];
    const int*   in_len  = (const int*)d_in[3];
    const int*   tgt_len = (const int*)d_in[4];

    // 4 no-op launches: last round ncu (-s 5 -c 1) caught the launch at our
    // index 4, so asg_main must sit at overall index 5 => 4 noops before it.
    for (int i = 0; i < 4; ++i) asg_noop<<<1, 1>>>();

    asg_main<<<BB, NTH>>>(trans, x, targets, in_len, tgt_len);
    asg_reduce<<<1, 128>>>((float*)d_out);
}